// round 15
// baseline (speedup 1.0000x reference)
#include <cuda_runtime.h>
#include <cuda_bf16.h>
#include <math.h>

// ---------------------------------------------------------------------------
// Problem constants
// ---------------------------------------------------------------------------
#define NN 100000     // nodes
#define EE 50000      // hyperedges
#define PP 1000000    // incidence pairs
#define KDIM 256      // IN_DIM
#define ODIM 128      // OUT_DIM
#define HID 32
#define NEG_SLOPE 0.2f

#define SCAN_BLK 512
#define SCAN_NB_N ((NN + SCAN_BLK - 1) / SCAN_BLK)   // 196
#define SCAN_NB_E ((EE + SCAN_BLK - 1) / SCAN_BLK)   // 98

#define WROWS 160     // packed GEMM output rows: [Wv(128); fc1_wx(32)]

// ---------------------------------------------------------------------------
// Device scratch (static allocation only)
// ---------------------------------------------------------------------------
__device__ uint2 g_WbigP[WROWS * (KDIM / 2)]; // pre-split (hi,lo) bf16x2 pairs
__device__ float g_tc[3 * HID];               // type_query @ fc1_w[:,256:].T
__device__ float g_wctx[3 * KDIM];            // Wq^T @ edge_ctx_t
__device__ float g_V[(size_t)NN * ODIM];
__device__ float g_H[(size_t)NN * HID];
__device__ float g_s3[NN * 4];                // raw scores x.wctx_t
__device__ float g_e3[NN * 4];                // exp(leaky(s)*alpha_type)
__device__ float g_dinv[EE];                  // INVERSE denominators
__device__ int   g_cntN[NN];
__device__ int   g_startN[NN + 1];
__device__ int   g_curN[NN];
__device__ int   g_cntE[EE];
__device__ int   g_startE[EE + 1];
__device__ int   g_curE[EE];
__device__ int   g_bsumN[SCAN_NB_N];
__device__ int   g_bsumE[SCAN_NB_E];
__device__ int   g_se[PP];                    // edge ids sorted by node
__device__ int   g_sn[PP];                    // node ids sorted by edge

// ---------------------------------------------------------------------------
// Helpers
// ---------------------------------------------------------------------------
__device__ __forceinline__ void mma_bf16(float* c, const unsigned* a, const unsigned* b) {
    asm volatile(
        "mma.sync.aligned.m16n8k16.row.col.f32.bf16.bf16.f32 "
        "{%0,%1,%2,%3}, {%4,%5,%6,%7}, {%8,%9}, {%0,%1,%2,%3};"
        : "+f"(c[0]), "+f"(c[1]), "+f"(c[2]), "+f"(c[3])
        : "r"(a[0]), "r"(a[1]), "r"(a[2]), "r"(a[3]), "r"(b[0]), "r"(b[1]));
}

__device__ __forceinline__ unsigned bf2pack(float a, float b) {
    __nv_bfloat162 h = __floats2bfloat162_rn(a, b);
    return *reinterpret_cast<unsigned*>(&h);
}

__device__ __forceinline__ uint2 split_pair(float v0, float v1) {
    float h0 = __bfloat162float(__float2bfloat16_rn(v0));
    float h1 = __bfloat162float(__float2bfloat16_rn(v1));
    uint2 r;
    r.x = bf2pack(h0, h1);
    r.y = bf2pack(v0 - h0, v1 - h1);
    return r;
}

__device__ __forceinline__ int warp_incl_scan(int x, int lane) {
    #pragma unroll
    for (int o = 1; o < 32; o <<= 1) {
        int y = __shfl_up_sync(0xFFFFFFFFu, x, o);
        if (lane >= o) x += y;
    }
    return x;
}

// ---------------------------------------------------------------------------
// Kernel: pack + PRE-SPLIT weights [Wv; fc1_wx] into (hi,lo) bf16x2 pairs
// ---------------------------------------------------------------------------
__global__ void k_pack(const float* __restrict__ Wv,
                       const float* __restrict__ fc1_w,
                       const float* __restrict__ type_query) {
    int r = blockIdx.x;  // 0..159
    const float* src = (r < 128) ? Wv + (size_t)r * KDIM
                                 : fc1_w + (size_t)(r - 128) * 320;
    for (int kp = threadIdx.x; kp < KDIM / 2; kp += blockDim.x) {
        g_WbigP[r * (KDIM / 2) + kp] = split_pair(src[kp * 2], src[kp * 2 + 1]);
    }
    if (blockIdx.x == 0 && threadIdx.x < 96) {
        int t = threadIdx.x / 32, j = threadIdx.x % 32;
        float s = 0.f;
        #pragma unroll 8
        for (int d = 0; d < 64; d++)
            s += type_query[t * 64 + d] * fc1_w[j * 320 + 256 + d];
        g_tc[t * 32 + j] = s;
    }
}

// ---------------------------------------------------------------------------
// Kernel: wctx[t] = Wq^T @ edge_ctx[t]   (3 x 256)
// ---------------------------------------------------------------------------
__global__ void k_wctx(const float* __restrict__ Wq,
                       const float* __restrict__ edge_ctx) {
    int t = blockIdx.x;
    int k = threadIdx.x;
    float s = 0.f;
    #pragma unroll 8
    for (int j = 0; j < ODIM; j++)
        s += Wq[j * KDIM + k] * edge_ctx[t * ODIM + j];
    g_wctx[t * KDIM + k] = s;
}

// ---------------------------------------------------------------------------
// Kernel: raw scores s3[n][t] = x[n] . wctx[t]. One warp per node.
// ---------------------------------------------------------------------------
__global__ __launch_bounds__(256)
void k_score(const float* __restrict__ X) {
    int n = (blockIdx.x * blockDim.x + threadIdx.x) >> 5;
    int lane = threadIdx.x & 31;
    if (n >= NN) return;

    const float* xr = X + (size_t)n * KDIM + lane * 8;
    float4 xa = *(const float4*)(xr);
    float4 xb = *(const float4*)(xr + 4);

    #pragma unroll
    for (int t = 0; t < 3; t++) {
        const float* wr = g_wctx + t * KDIM + lane * 8;
        float4 wa = *(const float4*)(wr);
        float4 wb = *(const float4*)(wr + 4);
        float d = xa.x * wa.x + xa.y * wa.y + xa.z * wa.z + xa.w * wa.w
                + xb.x * wb.x + xb.y * wb.y + xb.z * wb.z + xb.w * wb.w;
        #pragma unroll
        for (int o = 16; o; o >>= 1) d += __shfl_xor_sync(0xFFFFFFFFu, d, o);
        if (lane == 0) g_s3[n * 4 + t] = d;
    }
}

// ---------------------------------------------------------------------------
// Sort kernels. `which`: 0 = node-sort, 1 = edge-sort.
// ---------------------------------------------------------------------------
__global__ void k_init() {
    int i = blockIdx.x * blockDim.x + threadIdx.x;
    if (i < NN) g_cntN[i] = 0;
    if (i < EE) g_cntE[i] = 0;
}

__global__ void k_hist(const int* __restrict__ node_idx,
                       const int* __restrict__ edge_idx) {
    int p = blockIdx.x * blockDim.x + threadIdx.x;
    if (p < PP) {
        atomicAdd(&g_cntN[node_idx[p]], 1);
        atomicAdd(&g_cntE[edge_idx[p]], 1);
    }
}

__global__ __launch_bounds__(SCAN_BLK)
void k_scanA(int which) {
    const int* cnt = which ? g_cntE : g_cntN;
    int* start     = which ? g_startE : g_startN;
    int* bsum      = which ? g_bsumE : g_bsumN;
    const int n    = which ? EE : NN;
    __shared__ int wsum[16];
    int tid = threadIdx.x, lane = tid & 31, wid = tid >> 5;
    int i = blockIdx.x * SCAN_BLK + tid;
    int v = (i < n) ? cnt[i] : 0;
    int x = warp_incl_scan(v, lane);
    if (lane == 31) wsum[wid] = x;
    __syncthreads();
    if (wid == 0) {
        int w = (lane < 16) ? wsum[lane] : 0;
        w = warp_incl_scan(w, lane);
        if (lane < 16) wsum[lane] = w;
    }
    __syncthreads();
    int excl = x - v + (wid ? wsum[wid - 1] : 0);
    if (i < n) start[i] = excl;
    if (tid == SCAN_BLK - 1) bsum[blockIdx.x] = excl + v;
}

__global__ __launch_bounds__(256)
void k_scanB(int which) {
    int* bsum = which ? g_bsumE : g_bsumN;
    const int nb = which ? SCAN_NB_E : SCAN_NB_N;
    __shared__ int wsum[8];
    int tid = threadIdx.x, lane = tid & 31, wid = tid >> 5;
    int v = (tid < nb) ? bsum[tid] : 0;
    int x = warp_incl_scan(v, lane);
    if (lane == 31) wsum[wid] = x;
    __syncthreads();
    if (wid == 0) {
        int w = (lane < 8) ? wsum[lane] : 0;
        w = warp_incl_scan(w, lane);
        if (lane < 8) wsum[lane] = w;
    }
    __syncthreads();
    int excl = x - v + (wid ? wsum[wid - 1] : 0);
    if (tid < nb) bsum[tid] = excl;
}

__global__ void k_scanC(int which) {
    int* start  = which ? g_startE : g_startN;
    int* cursor = which ? g_curE : g_curN;
    const int* bsum = which ? g_bsumE : g_bsumN;
    const int n = which ? EE : NN;
    int i = blockIdx.x * blockDim.x + threadIdx.x;
    if (i < n) {
        int s = start[i] + bsum[i / SCAN_BLK];
        start[i] = s;
        cursor[i] = s;
    }
    if (i == 0) start[n] = PP;
}

__global__ void k_scatterN(const int* __restrict__ node_idx,
                           const int* __restrict__ edge_idx) {
    int p = blockIdx.x * blockDim.x + threadIdx.x;
    if (p >= PP) return;
    int pos = atomicAdd(&g_curN[node_idx[p]], 1);
    g_se[pos] = edge_idx[p];
}

__global__ void k_scatterE(const int* __restrict__ node_idx,
                           const int* __restrict__ edge_idx) {
    int p = blockIdx.x * blockDim.x + threadIdx.x;
    if (p >= PP) return;
    int pos = atomicAdd(&g_curE[edge_idx[p]], 1);
    g_sn[pos] = node_idx[p];
}

// ---------------------------------------------------------------------------
// 3xBF16 tensor-core GEMM  C[100000 x 160] = x @ Wbig^T  (unchanged from R14)
// ---------------------------------------------------------------------------
#define GBM 128
#define GBN 160
#define GBK 32
#define NT_TILES 10
#define PITCHP 18
#define A_U2 (GBM * PITCHP)
#define B_U2 (GBN * PITCHP)
#define STAGE_U2 (A_U2 + B_U2)
#define GEMM_SMEM_BYTES (2 * STAGE_U2 * sizeof(uint2))   // 82944

__global__ __launch_bounds__(256, 1)
void k_gemm(const float* __restrict__ X) {
    extern __shared__ uint2 sm[];

    const int bm = blockIdx.x;
    const int m0 = bm * GBM;
    const int tid = threadIdx.x;
    const int wid = tid >> 5, lane = tid & 31;
    const int warp_m = wid & 3;
    const int warp_n = wid >> 2;
    const int gid = lane >> 2;
    const int tig = lane & 3;

    const int arow = tid >> 1;
    const int akh  = (tid & 1) * 16;

    float acc[2][NT_TILES][4];
    #pragma unroll
    for (int i = 0; i < 2; i++)
        #pragma unroll
        for (int j = 0; j < NT_TILES; j++)
            #pragma unroll
            for (int q = 0; q < 4; q++) acc[i][j][q] = 0.f;

    float4 a_reg[4];
    uint4  b_reg[5];

    auto load_regs = [&](int kt) {
        int gm = m0 + arow;
        if (gm < NN) {
            const float* src = X + (size_t)gm * KDIM + kt + akh;
            #pragma unroll
            for (int i = 0; i < 4; i++) a_reg[i] = *(const float4*)(src + i * 4);
        } else {
            #pragma unroll
            for (int i = 0; i < 4; i++) a_reg[i] = make_float4(0.f, 0.f, 0.f, 0.f);
        }
        const uint4* bsrc = (const uint4*)g_WbigP;
        int kt4 = kt >> 2;
        #pragma unroll
        for (int i = 0; i < 5; i++) {
            int idx = tid + i * 256;
            int r = idx >> 3, kq = idx & 7;
            b_reg[i] = bsrc[r * 64 + kt4 + kq];
        }
    };

    auto store_smem = [&](int buf) {
        uint2* As = sm + buf * STAGE_U2;
        uint2* Bs = As + A_U2;
        uint2* adst = As + arow * PITCHP + (akh >> 1);
        #pragma unroll
        for (int i = 0; i < 4; i++) {
            adst[i * 2    ] = split_pair(a_reg[i].x, a_reg[i].y);
            adst[i * 2 + 1] = split_pair(a_reg[i].z, a_reg[i].w);
        }
        #pragma unroll
        for (int i = 0; i < 5; i++) {
            int idx = tid + i * 256;
            int r = idx >> 3, kq = idx & 7;
            *(uint4*)(Bs + r * PITCHP + kq * 2) = b_reg[i];
        }
    };

    auto compute = [&](int buf) {
        const uint2* As = sm + buf * STAGE_U2;
        const uint2* Bs = As + A_U2;
        #pragma unroll
        for (int ks = 0; ks < 2; ks++) {
            int kb = ks * 8;
            unsigned ahi[2][4], alo[2][4];
            #pragma unroll
            for (int mt = 0; mt < 2; mt++) {
                int rb = warp_m * 32 + mt * 16;
                uint2 a0 = As[(rb + gid    ) * PITCHP + kb + tig    ];
                uint2 a1 = As[(rb + gid + 8) * PITCHP + kb + tig    ];
                uint2 a2 = As[(rb + gid    ) * PITCHP + kb + tig + 4];
                uint2 a3 = As[(rb + gid + 8) * PITCHP + kb + tig + 4];
                ahi[mt][0] = a0.x; ahi[mt][1] = a1.x; ahi[mt][2] = a2.x; ahi[mt][3] = a3.x;
                alo[mt][0] = a0.y; alo[mt][1] = a1.y; alo[mt][2] = a2.y; alo[mt][3] = a3.y;
            }
            #pragma unroll
            for (int nt = 0; nt < NT_TILES; nt++) {
                int cb = warp_n * 80 + nt * 8 + gid;
                uint2 u0 = Bs[cb * PITCHP + kb + tig    ];
                uint2 u1 = Bs[cb * PITCHP + kb + tig + 4];
                unsigned bhi[2] = {u0.x, u1.x};
                unsigned blo[2] = {u0.y, u1.y};
                #pragma unroll
                for (int mt = 0; mt < 2; mt++) {
                    mma_bf16(acc[mt][nt], ahi[mt], bhi);
                    mma_bf16(acc[mt][nt], ahi[mt], blo);
                    mma_bf16(acc[mt][nt], alo[mt], bhi);
                }
            }
        }
    };

    const int NT = KDIM / GBK;
    load_regs(0);
    store_smem(0);
    __syncthreads();
    load_regs(GBK);
    for (int t = 0; t < NT; t++) {
        compute(t & 1);
        if (t + 1 < NT) {
            store_smem((t + 1) & 1);
            __syncthreads();
            if (t + 2 < NT) load_regs((t + 2) * GBK);
        }
    }

    #pragma unroll
    for (int mt = 0; mt < 2; mt++) {
        int mbase = m0 + warp_m * 32 + mt * 16;
        int r0 = mbase + gid, r1 = mbase + gid + 8;
        #pragma unroll
        for (int nt = 0; nt < NT_TILES; nt++) {
            int col = warp_n * 80 + nt * 8 + tig * 2;
            float2 v0 = make_float2(acc[mt][nt][0], acc[mt][nt][1]);
            float2 v1 = make_float2(acc[mt][nt][2], acc[mt][nt][3]);
            if (col < 128) {
                if (r0 < NN) *(float2*)(g_V + (size_t)r0 * ODIM + col) = v0;
                if (r1 < NN) *(float2*)(g_V + (size_t)r1 * ODIM + col) = v1;
            } else {
                if (r0 < NN) *(float2*)(g_H + (size_t)r0 * HID + col - 128) = v0;
                if (r1 < NN) *(float2*)(g_H + (size_t)r1 * HID + col - 128) = v1;
            }
        }
    }
}

// ---------------------------------------------------------------------------
// Kernel: gate only. One warp per node.
// ---------------------------------------------------------------------------
__global__ __launch_bounds__(256)
void k_gate(const int*   __restrict__ node_types,
            const float* __restrict__ fc1_b,
            const float* __restrict__ fc2_w,
            const float* __restrict__ fc2_b) {
    int n = (blockIdx.x * blockDim.x + threadIdx.x) >> 5;
    int lane = threadIdx.x & 31;
    if (n >= NN) return;

    int ty = node_types[n];
    float hv = tanhf(g_H[(size_t)n * HID + lane] + g_tc[ty * 32 + lane] + fc1_b[lane]);
    float gacc = hv * fc2_w[lane];
    #pragma unroll
    for (int o = 16; o; o >>= 1) gacc += __shfl_xor_sync(0xFFFFFFFFu, gacc, o);
    float at = 1.f / (1.f + __expf(-(gacc + fc2_b[0])));

    if (lane < 3) {
        float a = g_s3[n * 4 + lane];
        a = (a >= 0.f) ? a : NEG_SLOPE * a;
        g_e3[n * 4 + lane] = __expf(a * at);
    }
}

// ---------------------------------------------------------------------------
// pass C (edge-centric): one warp per edge, 4-way unrolled gather.
// Register denominator; writes NORMALIZED edge_feat + inverse denom.
// ---------------------------------------------------------------------------
__global__ __launch_bounds__(256)
void k_passC(const int* __restrict__ edge_type,
             float* __restrict__ edge_feat) {
    int e = (blockIdx.x * blockDim.x + threadIdx.x) >> 5;
    int lane = threadIdx.x & 31;
    if (e >= EE) return;
    int s = g_startE[e], epos = g_startE[e + 1];
    int t = edge_type[e];

    float4 acc = make_float4(0.f, 0.f, 0.f, 0.f);
    float denom = 0.f;

    int i = s;
    for (; i + 3 < epos; i += 4) {
        int n0 = g_sn[i], n1 = g_sn[i + 1], n2 = g_sn[i + 2], n3 = g_sn[i + 3];
        float ea0 = __ldg(&g_e3[n0 * 4 + t]);
        float ea1 = __ldg(&g_e3[n1 * 4 + t]);
        float ea2 = __ldg(&g_e3[n2 * 4 + t]);
        float ea3 = __ldg(&g_e3[n3 * 4 + t]);
        float4 v0 = *(const float4*)(g_V + (size_t)n0 * ODIM + lane * 4);
        float4 v1 = *(const float4*)(g_V + (size_t)n1 * ODIM + lane * 4);
        float4 v2 = *(const float4*)(g_V + (size_t)n2 * ODIM + lane * 4);
        float4 v3 = *(const float4*)(g_V + (size_t)n3 * ODIM + lane * 4);
        denom += (ea0 + ea1) + (ea2 + ea3);
        acc.x += ea0 * v0.x + ea1 * v1.x + ea2 * v2.x + ea3 * v3.x;
        acc.y += ea0 * v0.y + ea1 * v1.y + ea2 * v2.y + ea3 * v3.y;
        acc.z += ea0 * v0.z + ea1 * v1.z + ea2 * v2.z + ea3 * v3.z;
        acc.w += ea0 * v0.w + ea1 * v1.w + ea2 * v2.w + ea3 * v3.w;
    }
    for (; i < epos; i++) {
        int n0 = g_sn[i];
        float ea0 = __ldg(&g_e3[n0 * 4 + t]);
        float4 v0 = *(const float4*)(g_V + (size_t)n0 * ODIM + lane * 4);
        denom += ea0;
        acc.x += ea0 * v0.x; acc.y += ea0 * v0.y;
        acc.z += ea0 * v0.z; acc.w += ea0 * v0.w;
    }

    float inv = (denom > 0.f) ? 1.f / denom : 0.f;
    *(float4*)(edge_feat + (size_t)e * ODIM + lane * 4) =
        make_float4(acc.x * inv, acc.y * inv, acc.z * inv, acc.w * inv);
    if (lane == 0) g_dinv[e] = inv;
}

// ---------------------------------------------------------------------------
// pass D: one warp per node, 4-way unrolled gather; multiply by inv denom.
// ---------------------------------------------------------------------------
__global__ __launch_bounds__(256)
void k_passD(const int* __restrict__ edge_type,
             const float* __restrict__ edge_feat,
             float* __restrict__ node_feat) {
    int n = (blockIdx.x * blockDim.x + threadIdx.x) >> 5;
    int lane = threadIdx.x & 31;
    if (n >= NN) return;
    int s = g_startN[n], epos = g_startN[n + 1];

    float4 acc = make_float4(0.f, 0.f, 0.f, 0.f);
    float4 e3 = *(const float4*)(g_e3 + n * 4);

    int i = s;
    for (; i + 3 < epos; i += 4) {
        int e0 = g_se[i], e1 = g_se[i + 1], e2 = g_se[i + 2], e3i = g_se[i + 3];
        int t0 = __ldg(&edge_type[e0]), t1 = __ldg(&edge_type[e1]);
        int t2 = __ldg(&edge_type[e2]), t3 = __ldg(&edge_type[e3i]);
        float num0 = (t0 == 0) ? e3.x : (t0 == 1) ? e3.y : e3.z;
        float num1 = (t1 == 0) ? e3.x : (t1 == 1) ? e3.y : e3.z;
        float num2 = (t2 == 0) ? e3.x : (t2 == 1) ? e3.y : e3.z;
        float num3 = (t3 == 0) ? e3.x : (t3 == 1) ? e3.y : e3.z;
        float a0 = num0 * __ldg(&g_dinv[e0]);
        float a1 = num1 * __ldg(&g_dinv[e1]);
        float a2 = num2 * __ldg(&g_dinv[e2]);
        float a3 = num3 * __ldg(&g_dinv[e3i]);
        float4 f0 = *(const float4*)(edge_feat + (size_t)e0 * ODIM + lane * 4);
        float4 f1 = *(const float4*)(edge_feat + (size_t)e1 * ODIM + lane * 4);
        float4 f2 = *(const float4*)(edge_feat + (size_t)e2 * ODIM + lane * 4);
        float4 f3 = *(const float4*)(edge_feat + (size_t)e3i * ODIM + lane * 4);
        acc.x += a0 * f0.x + a1 * f1.x + a2 * f2.x + a3 * f3.x;
        acc.y += a0 * f0.y + a1 * f1.y + a2 * f2.y + a3 * f3.y;
        acc.z += a0 * f0.z + a1 * f1.z + a2 * f2.z + a3 * f3.z;
        acc.w += a0 * f0.w + a1 * f1.w + a2 * f2.w + a3 * f3.w;
    }
    for (; i < epos; i++) {
        int e0 = g_se[i];
        int t0 = __ldg(&edge_type[e0]);
        float num0 = (t0 == 0) ? e3.x : (t0 == 1) ? e3.y : e3.z;
        float a0 = num0 * __ldg(&g_dinv[e0]);
        float4 f0 = *(const float4*)(edge_feat + (size_t)e0 * ODIM + lane * 4);
        acc.x += a0 * f0.x; acc.y += a0 * f0.y;
        acc.z += a0 * f0.z; acc.w += a0 * f0.w;
    }
    *(float4*)(node_feat + (size_t)n * ODIM + lane * 4) = acc;
}

// ---------------------------------------------------------------------------
// Launch: 3 streams, fine-grained joins (same DAG as R13/R14).
// ---------------------------------------------------------------------------
extern "C" void kernel_launch(void* const* d_in, const int* in_sizes, int n_in,
                              void* d_out, int out_size) {
    const float* x          = (const float*)d_in[0];
    const int*   node_types = (const int*)  d_in[1];
    const int*   edge_type  = (const int*)  d_in[2];
    const int*   node_idx   = (const int*)  d_in[3];
    const int*   edge_idx   = (const int*)  d_in[4];
    const float* type_query = (const float*)d_in[5];
    const float* fc1_w      = (const float*)d_in[6];
    const float* fc1_b      = (const float*)d_in[7];
    const float* fc2_w      = (const float*)d_in[8];
    const float* fc2_b      = (const float*)d_in[9];
    const float* Wq         = (const float*)d_in[10];
    const float* Wv         = (const float*)d_in[11];
    const float* edge_ctx   = (const float*)d_in[12];

    float* node_feat = (float*)d_out;                       // N x 128
    float* edge_feat = (float*)d_out + (size_t)NN * ODIM;   // E x 128

    static cudaStream_t s2 = nullptr, s3 = nullptr;
    static cudaEvent_t evFork = nullptr, evHist = nullptr, evScore = nullptr,
                       evN = nullptr, evE = nullptr;
    if (s2 == nullptr) {
        cudaStreamCreateWithFlags(&s2, cudaStreamNonBlocking);
        cudaStreamCreateWithFlags(&s3, cudaStreamNonBlocking);
        cudaEventCreateWithFlags(&evFork, cudaEventDisableTiming);
        cudaEventCreateWithFlags(&evHist, cudaEventDisableTiming);
        cudaEventCreateWithFlags(&evScore, cudaEventDisableTiming);
        cudaEventCreateWithFlags(&evN, cudaEventDisableTiming);
        cudaEventCreateWithFlags(&evE, cudaEventDisableTiming);
        cudaFuncSetAttribute(k_gemm, cudaFuncAttributeMaxDynamicSharedMemorySize,
                             GEMM_SMEM_BYTES);
    }

    // ---- fork ----
    cudaEventRecord(evFork, 0);
    cudaStreamWaitEvent(s2, evFork, 0);
    cudaStreamWaitEvent(s3, evFork, 0);

    // s2: histogram + node sort
    k_init<<<(NN + 255) / 256, 256, 0, s2>>>();
    k_hist<<<(PP + 255) / 256, 256, 0, s2>>>(node_idx, edge_idx);
    cudaEventRecord(evHist, s2);
    k_scanA<<<SCAN_NB_N, SCAN_BLK, 0, s2>>>(0);
    k_scanB<<<1, 256, 0, s2>>>(0);
    k_scanC<<<(NN + 255) / 256, 256, 0, s2>>>(0);
    k_scatterN<<<(PP + 255) / 256, 256, 0, s2>>>(node_idx, edge_idx);
    cudaEventRecord(evN, s2);

    // s3: scores, then edge sort (after histogram)
    k_wctx<<<3, 256, 0, s3>>>(Wq, edge_ctx);
    k_score<<<(NN * 32 + 255) / 256, 256, 0, s3>>>(x);
    cudaEventRecord(evScore, s3);
    cudaStreamWaitEvent(s3, evHist, 0);
    k_scanA<<<SCAN_NB_E, SCAN_BLK, 0, s3>>>(1);
    k_scanB<<<1, 256, 0, s3>>>(1);
    k_scanC<<<(EE + 255) / 256, 256, 0, s3>>>(1);
    k_scatterE<<<(PP + 255) / 256, 256, 0, s3>>>(node_idx, edge_idx);
    cudaEventRecord(evE, s3);

    // main: dense pipeline
    k_pack<<<WROWS, 128>>>(Wv, fc1_w, type_query);
    k_gemm<<<(NN + GBM - 1) / GBM, 256, GEMM_SMEM_BYTES>>>(x);

    cudaStreamWaitEvent(0, evScore, 0);
    k_gate<<<(NN * 32 + 255) / 256, 256>>>(node_types, fc1_b, fc2_w, fc2_b);

    cudaStreamWaitEvent(0, evE, 0);
    k_passC<<<(EE * 32 + 255) / 256, 256>>>(edge_type, edge_feat);

    cudaStreamWaitEvent(0, evN, 0);
    int node_warp_blocks = (NN * 32 + 255) / 256;
    k_passD<<<node_warp_blocks, 256>>>(edge_type, edge_feat, node_feat);
}

// round 16
// speedup vs baseline: 1.0320x; 1.0320x over previous
#include <cuda_runtime.h>
#include <cuda_bf16.h>
#include <math.h>

// ---------------------------------------------------------------------------
// Problem constants
// ---------------------------------------------------------------------------
#define NN 100000     // nodes
#define EE 50000      // hyperedges
#define PP 1000000    // incidence pairs
#define KDIM 256      // IN_DIM
#define ODIM 128      // OUT_DIM
#define HID 32
#define NEG_SLOPE 0.2f

#define SCAN_BLK 512
#define SCAN_NB_E ((EE + SCAN_BLK - 1) / SCAN_BLK)   // 98

#define WROWS 160     // packed GEMM output rows: [Wv(128); fc1_wx(32)]

// ---------------------------------------------------------------------------
// Device scratch (static allocation only)
// ---------------------------------------------------------------------------
__device__ uint2 g_WbigP[WROWS * (KDIM / 2)]; // pre-split (hi,lo) bf16x2 pairs
__device__ float g_tc[3 * HID];               // type_query @ fc1_w[:,256:].T
__device__ float g_wctx[3 * KDIM];            // Wq^T @ edge_ctx_t
__device__ float g_V[(size_t)NN * ODIM];
__device__ float g_H[(size_t)NN * HID];
__device__ float g_s3[NN * 4];                // raw scores x.wctx_t
__device__ float g_e3[NN * 4];                // exp(leaky(s)*alpha_type)
__device__ int   g_cntE[EE];
__device__ int   g_startE[EE + 1];
__device__ int   g_curE[EE];
__device__ int   g_bsumE[SCAN_NB_E];
__device__ int   g_sn[PP];                    // node ids sorted by edge

// ---------------------------------------------------------------------------
// Helpers
// ---------------------------------------------------------------------------
__device__ __forceinline__ void red_add_v4(float* addr, float4 v) {
    asm volatile("red.global.add.v4.f32 [%0], {%1,%2,%3,%4};"
                 :: "l"(addr), "f"(v.x), "f"(v.y), "f"(v.z), "f"(v.w)
                 : "memory");
}

__device__ __forceinline__ void mma_bf16(float* c, const unsigned* a, const unsigned* b) {
    asm volatile(
        "mma.sync.aligned.m16n8k16.row.col.f32.bf16.bf16.f32 "
        "{%0,%1,%2,%3}, {%4,%5,%6,%7}, {%8,%9}, {%0,%1,%2,%3};"
        : "+f"(c[0]), "+f"(c[1]), "+f"(c[2]), "+f"(c[3])
        : "r"(a[0]), "r"(a[1]), "r"(a[2]), "r"(a[3]), "r"(b[0]), "r"(b[1]));
}

__device__ __forceinline__ unsigned bf2pack(float a, float b) {
    __nv_bfloat162 h = __floats2bfloat162_rn(a, b);
    return *reinterpret_cast<unsigned*>(&h);
}

__device__ __forceinline__ uint2 split_pair(float v0, float v1) {
    float h0 = __bfloat162float(__float2bfloat16_rn(v0));
    float h1 = __bfloat162float(__float2bfloat16_rn(v1));
    uint2 r;
    r.x = bf2pack(h0, h1);
    r.y = bf2pack(v0 - h0, v1 - h1);
    return r;
}

__device__ __forceinline__ int warp_incl_scan(int x, int lane) {
    #pragma unroll
    for (int o = 1; o < 32; o <<= 1) {
        int y = __shfl_up_sync(0xFFFFFFFFu, x, o);
        if (lane >= o) x += y;
    }
    return x;
}

// ---------------------------------------------------------------------------
// Kernel: pack + PRE-SPLIT weights [Wv; fc1_wx] into (hi,lo) bf16x2 pairs
// ---------------------------------------------------------------------------
__global__ void k_pack(const float* __restrict__ Wv,
                       const float* __restrict__ fc1_w,
                       const float* __restrict__ type_query) {
    int r = blockIdx.x;  // 0..159
    const float* src = (r < 128) ? Wv + (size_t)r * KDIM
                                 : fc1_w + (size_t)(r - 128) * 320;
    for (int kp = threadIdx.x; kp < KDIM / 2; kp += blockDim.x) {
        g_WbigP[r * (KDIM / 2) + kp] = split_pair(src[kp * 2], src[kp * 2 + 1]);
    }
    if (blockIdx.x == 0 && threadIdx.x < 96) {
        int t = threadIdx.x / 32, j = threadIdx.x % 32;
        float s = 0.f;
        #pragma unroll 8
        for (int d = 0; d < 64; d++)
            s += type_query[t * 64 + d] * fc1_w[j * 320 + 256 + d];
        g_tc[t * 32 + j] = s;
    }
}

// ---------------------------------------------------------------------------
// Kernel: wctx[t] = Wq^T @ edge_ctx[t]   (3 x 256)
// ---------------------------------------------------------------------------
__global__ void k_wctx(const float* __restrict__ Wq,
                       const float* __restrict__ edge_ctx) {
    int t = blockIdx.x;
    int k = threadIdx.x;
    float s = 0.f;
    #pragma unroll 8
    for (int j = 0; j < ODIM; j++)
        s += Wq[j * KDIM + k] * edge_ctx[t * ODIM + j];
    g_wctx[t * KDIM + k] = s;
}

// ---------------------------------------------------------------------------
// Kernel: raw scores s3[n][t] = x[n] . wctx[t]. One warp per node.
// ---------------------------------------------------------------------------
__global__ __launch_bounds__(256)
void k_score(const float* __restrict__ X) {
    int n = (blockIdx.x * blockDim.x + threadIdx.x) >> 5;
    int lane = threadIdx.x & 31;
    if (n >= NN) return;

    const float* xr = X + (size_t)n * KDIM + lane * 8;
    float4 xa = *(const float4*)(xr);
    float4 xb = *(const float4*)(xr + 4);

    #pragma unroll
    for (int t = 0; t < 3; t++) {
        const float* wr = g_wctx + t * KDIM + lane * 8;
        float4 wa = *(const float4*)(wr);
        float4 wb = *(const float4*)(wr + 4);
        float d = xa.x * wa.x + xa.y * wa.y + xa.z * wa.z + xa.w * wa.w
                + xb.x * wb.x + xb.y * wb.y + xb.z * wb.z + xb.w * wb.w;
        #pragma unroll
        for (int o = 16; o; o >>= 1) d += __shfl_xor_sync(0xFFFFFFFFu, d, o);
        if (lane == 0) g_s3[n * 4 + t] = d;
    }
}

// ---------------------------------------------------------------------------
// Edge sort kernels (node sort no longer needed)
// ---------------------------------------------------------------------------
__global__ void k_init() {
    int i = blockIdx.x * blockDim.x + threadIdx.x;
    if (i < EE) g_cntE[i] = 0;
}

__global__ void k_hist(const int* __restrict__ edge_idx) {
    int p = blockIdx.x * blockDim.x + threadIdx.x;
    if (p < PP) atomicAdd(&g_cntE[edge_idx[p]], 1);
}

__global__ __launch_bounds__(SCAN_BLK)
void k_scanA() {
    __shared__ int wsum[16];
    int tid = threadIdx.x, lane = tid & 31, wid = tid >> 5;
    int i = blockIdx.x * SCAN_BLK + tid;
    int v = (i < EE) ? g_cntE[i] : 0;
    int x = warp_incl_scan(v, lane);
    if (lane == 31) wsum[wid] = x;
    __syncthreads();
    if (wid == 0) {
        int w = (lane < 16) ? wsum[lane] : 0;
        w = warp_incl_scan(w, lane);
        if (lane < 16) wsum[lane] = w;
    }
    __syncthreads();
    int excl = x - v + (wid ? wsum[wid - 1] : 0);
    if (i < EE) g_startE[i] = excl;
    if (tid == SCAN_BLK - 1) g_bsumE[blockIdx.x] = excl + v;
}

__global__ __launch_bounds__(256)
void k_scanB() {
    __shared__ int wsum[8];
    int tid = threadIdx.x, lane = tid & 31, wid = tid >> 5;
    int v = (tid < SCAN_NB_E) ? g_bsumE[tid] : 0;
    int x = warp_incl_scan(v, lane);
    if (lane == 31) wsum[wid] = x;
    __syncthreads();
    if (wid == 0) {
        int w = (lane < 8) ? wsum[lane] : 0;
        w = warp_incl_scan(w, lane);
        if (lane < 8) wsum[lane] = w;
    }
    __syncthreads();
    int excl = x - v + (wid ? wsum[wid - 1] : 0);
    if (tid < SCAN_NB_E) g_bsumE[tid] = excl;
}

__global__ void k_scanC() {
    int i = blockIdx.x * blockDim.x + threadIdx.x;
    if (i < EE) {
        int s = g_startE[i] + g_bsumE[i / SCAN_BLK];
        g_startE[i] = s;
        g_curE[i] = s;
    }
    if (i == 0) g_startE[EE] = PP;
}

__global__ void k_scatterE(const int* __restrict__ node_idx,
                           const int* __restrict__ edge_idx) {
    int p = blockIdx.x * blockDim.x + threadIdx.x;
    if (p >= PP) return;
    int pos = atomicAdd(&g_curE[edge_idx[p]], 1);
    g_sn[pos] = node_idx[p];
}

// ---------------------------------------------------------------------------
// 3xBF16 tensor-core GEMM  C[100000 x 160] = x @ Wbig^T  (unchanged from R14)
// ---------------------------------------------------------------------------
#define GBM 128
#define GBN 160
#define GBK 32
#define NT_TILES 10
#define PITCHP 18
#define A_U2 (GBM * PITCHP)
#define B_U2 (GBN * PITCHP)
#define STAGE_U2 (A_U2 + B_U2)
#define GEMM_SMEM_BYTES (2 * STAGE_U2 * sizeof(uint2))   // 82944

__global__ __launch_bounds__(256, 1)
void k_gemm(const float* __restrict__ X) {
    extern __shared__ uint2 sm[];

    const int bm = blockIdx.x;
    const int m0 = bm * GBM;
    const int tid = threadIdx.x;
    const int wid = tid >> 5, lane = tid & 31;
    const int warp_m = wid & 3;
    const int warp_n = wid >> 2;
    const int gid = lane >> 2;
    const int tig = lane & 3;

    const int arow = tid >> 1;
    const int akh  = (tid & 1) * 16;

    float acc[2][NT_TILES][4];
    #pragma unroll
    for (int i = 0; i < 2; i++)
        #pragma unroll
        for (int j = 0; j < NT_TILES; j++)
            #pragma unroll
            for (int q = 0; q < 4; q++) acc[i][j][q] = 0.f;

    float4 a_reg[4];
    uint4  b_reg[5];

    auto load_regs = [&](int kt) {
        int gm = m0 + arow;
        if (gm < NN) {
            const float* src = X + (size_t)gm * KDIM + kt + akh;
            #pragma unroll
            for (int i = 0; i < 4; i++) a_reg[i] = *(const float4*)(src + i * 4);
        } else {
            #pragma unroll
            for (int i = 0; i < 4; i++) a_reg[i] = make_float4(0.f, 0.f, 0.f, 0.f);
        }
        const uint4* bsrc = (const uint4*)g_WbigP;
        int kt4 = kt >> 2;
        #pragma unroll
        for (int i = 0; i < 5; i++) {
            int idx = tid + i * 256;
            int r = idx >> 3, kq = idx & 7;
            b_reg[i] = bsrc[r * 64 + kt4 + kq];
        }
    };

    auto store_smem = [&](int buf) {
        uint2* As = sm + buf * STAGE_U2;
        uint2* Bs = As + A_U2;
        uint2* adst = As + arow * PITCHP + (akh >> 1);
        #pragma unroll
        for (int i = 0; i < 4; i++) {
            adst[i * 2    ] = split_pair(a_reg[i].x, a_reg[i].y);
            adst[i * 2 + 1] = split_pair(a_reg[i].z, a_reg[i].w);
        }
        #pragma unroll
        for (int i = 0; i < 5; i++) {
            int idx = tid + i * 256;
            int r = idx >> 3, kq = idx & 7;
            *(uint4*)(Bs + r * PITCHP + kq * 2) = b_reg[i];
        }
    };

    auto compute = [&](int buf) {
        const uint2* As = sm + buf * STAGE_U2;
        const uint2* Bs = As + A_U2;
        #pragma unroll
        for (int ks = 0; ks < 2; ks++) {
            int kb = ks * 8;
            unsigned ahi[2][4], alo[2][4];
            #pragma unroll
            for (int mt = 0; mt < 2; mt++) {
                int rb = warp_m * 32 + mt * 16;
                uint2 a0 = As[(rb + gid    ) * PITCHP + kb + tig    ];
                uint2 a1 = As[(rb + gid + 8) * PITCHP + kb + tig    ];
                uint2 a2 = As[(rb + gid    ) * PITCHP + kb + tig + 4];
                uint2 a3 = As[(rb + gid + 8) * PITCHP + kb + tig + 4];
                ahi[mt][0] = a0.x; ahi[mt][1] = a1.x; ahi[mt][2] = a2.x; ahi[mt][3] = a3.x;
                alo[mt][0] = a0.y; alo[mt][1] = a1.y; alo[mt][2] = a2.y; alo[mt][3] = a3.y;
            }
            #pragma unroll
            for (int nt = 0; nt < NT_TILES; nt++) {
                int cb = warp_n * 80 + nt * 8 + gid;
                uint2 u0 = Bs[cb * PITCHP + kb + tig    ];
                uint2 u1 = Bs[cb * PITCHP + kb + tig + 4];
                unsigned bhi[2] = {u0.x, u1.x};
                unsigned blo[2] = {u0.y, u1.y};
                #pragma unroll
                for (int mt = 0; mt < 2; mt++) {
                    mma_bf16(acc[mt][nt], ahi[mt], bhi);
                    mma_bf16(acc[mt][nt], ahi[mt], blo);
                    mma_bf16(acc[mt][nt], alo[mt], bhi);
                }
            }
        }
    };

    const int NT = KDIM / GBK;
    load_regs(0);
    store_smem(0);
    __syncthreads();
    load_regs(GBK);
    for (int t = 0; t < NT; t++) {
        compute(t & 1);
        if (t + 1 < NT) {
            store_smem((t + 1) & 1);
            __syncthreads();
            if (t + 2 < NT) load_regs((t + 2) * GBK);
        }
    }

    #pragma unroll
    for (int mt = 0; mt < 2; mt++) {
        int mbase = m0 + warp_m * 32 + mt * 16;
        int r0 = mbase + gid, r1 = mbase + gid + 8;
        #pragma unroll
        for (int nt = 0; nt < NT_TILES; nt++) {
            int col = warp_n * 80 + nt * 8 + tig * 2;
            float2 v0 = make_float2(acc[mt][nt][0], acc[mt][nt][1]);
            float2 v1 = make_float2(acc[mt][nt][2], acc[mt][nt][3]);
            if (col < 128) {
                if (r0 < NN) *(float2*)(g_V + (size_t)r0 * ODIM + col) = v0;
                if (r1 < NN) *(float2*)(g_V + (size_t)r1 * ODIM + col) = v1;
            } else {
                if (r0 < NN) *(float2*)(g_H + (size_t)r0 * HID + col - 128) = v0;
                if (r1 < NN) *(float2*)(g_H + (size_t)r1 * HID + col - 128) = v1;
            }
        }
    }
}

// ---------------------------------------------------------------------------
// Kernel: gate only. One warp per node.
// ---------------------------------------------------------------------------
__global__ __launch_bounds__(256)
void k_gate(const int*   __restrict__ node_types,
            const float* __restrict__ fc1_b,
            const float* __restrict__ fc2_w,
            const float* __restrict__ fc2_b) {
    int n = (blockIdx.x * blockDim.x + threadIdx.x) >> 5;
    int lane = threadIdx.x & 31;
    if (n >= NN) return;

    int ty = node_types[n];
    float hv = tanhf(g_H[(size_t)n * HID + lane] + g_tc[ty * 32 + lane] + fc1_b[lane]);
    float gacc = hv * fc2_w[lane];
    #pragma unroll
    for (int o = 16; o; o >>= 1) gacc += __shfl_xor_sync(0xFFFFFFFFu, gacc, o);
    float at = 1.f / (1.f + __expf(-(gacc + fc2_b[0])));

    if (lane < 3) {
        float a = g_s3[n * 4 + lane];
        a = (a >= 0.f) ? a : NEG_SLOPE * a;
        g_e3[n * 4 + lane] = __expf(a * at);
    }
}

// ---------------------------------------------------------------------------
// FUSED pass C+D: one warp per edge.
// Loop 1: gather members' ea*V -> registers; denominator in-register.
// Write normalized edge_feat.
// Loop 2: re-walk members, red.add attn_ne * f into node_feat.
// No node sort, no separate pass D, no edge_feat re-read.
// ---------------------------------------------------------------------------
__global__ __launch_bounds__(256)
void k_passCD(const int* __restrict__ edge_type,
              float* __restrict__ edge_feat,
              float* __restrict__ node_feat) {
    int e = (blockIdx.x * blockDim.x + threadIdx.x) >> 5;
    int lane = threadIdx.x & 31;
    if (e >= EE) return;
    int s = g_startE[e], epos = g_startE[e + 1];
    int t = edge_type[e];

    float4 acc = make_float4(0.f, 0.f, 0.f, 0.f);
    float denom = 0.f;

    int i = s;
    for (; i + 1 < epos; i += 2) {
        int n0 = g_sn[i], n1 = g_sn[i + 1];
        float ea0 = __ldg(&g_e3[n0 * 4 + t]);
        float ea1 = __ldg(&g_e3[n1 * 4 + t]);
        float4 v0 = *(const float4*)(g_V + (size_t)n0 * ODIM + lane * 4);
        float4 v1 = *(const float4*)(g_V + (size_t)n1 * ODIM + lane * 4);
        denom += ea0 + ea1;
        acc.x += ea0 * v0.x + ea1 * v1.x;
        acc.y += ea0 * v0.y + ea1 * v1.y;
        acc.z += ea0 * v0.z + ea1 * v1.z;
        acc.w += ea0 * v0.w + ea1 * v1.w;
    }
    if (i < epos) {
        int n0 = g_sn[i];
        float ea0 = __ldg(&g_e3[n0 * 4 + t]);
        float4 v0 = *(const float4*)(g_V + (size_t)n0 * ODIM + lane * 4);
        denom += ea0;
        acc.x += ea0 * v0.x; acc.y += ea0 * v0.y;
        acc.z += ea0 * v0.z; acc.w += ea0 * v0.w;
    }

    float inv = (denom > 0.f) ? 1.f / denom : 0.f;
    float4 f = make_float4(acc.x * inv, acc.y * inv, acc.z * inv, acc.w * inv);
    *(float4*)(edge_feat + (size_t)e * ODIM + lane * 4) = f;

    // Loop 2: scatter attn * f into node_feat (atomic vector reduction)
    for (int j = s; j < epos; j++) {
        int n0 = g_sn[j];
        float attn = __ldg(&g_e3[n0 * 4 + t]) * inv;
        red_add_v4(node_feat + (size_t)n0 * ODIM + lane * 4,
                   make_float4(attn * f.x, attn * f.y, attn * f.z, attn * f.w));
    }
}

// ---------------------------------------------------------------------------
// Launch: 2 side streams.
//   s2: memset node_feat, init/hist, edge sort -> evE
//   s3: wctx/score -> evScore
//   main: pack, GEMM -> [evScore] gate -> [evE] fused passCD
// ---------------------------------------------------------------------------
extern "C" void kernel_launch(void* const* d_in, const int* in_sizes, int n_in,
                              void* d_out, int out_size) {
    const float* x          = (const float*)d_in[0];
    const int*   node_types = (const int*)  d_in[1];
    const int*   edge_type  = (const int*)  d_in[2];
    const int*   node_idx   = (const int*)  d_in[3];
    const int*   edge_idx   = (const int*)  d_in[4];
    const float* type_query = (const float*)d_in[5];
    const float* fc1_w      = (const float*)d_in[6];
    const float* fc1_b      = (const float*)d_in[7];
    const float* fc2_w      = (const float*)d_in[8];
    const float* fc2_b      = (const float*)d_in[9];
    const float* Wq         = (const float*)d_in[10];
    const float* Wv         = (const float*)d_in[11];
    const float* edge_ctx   = (const float*)d_in[12];

    float* node_feat = (float*)d_out;                       // N x 128
    float* edge_feat = (float*)d_out + (size_t)NN * ODIM;   // E x 128

    static cudaStream_t s2 = nullptr, s3 = nullptr;
    static cudaEvent_t evFork = nullptr, evScore = nullptr, evE = nullptr;
    if (s2 == nullptr) {
        cudaStreamCreateWithFlags(&s2, cudaStreamNonBlocking);
        cudaStreamCreateWithFlags(&s3, cudaStreamNonBlocking);
        cudaEventCreateWithFlags(&evFork, cudaEventDisableTiming);
        cudaEventCreateWithFlags(&evScore, cudaEventDisableTiming);
        cudaEventCreateWithFlags(&evE, cudaEventDisableTiming);
        cudaFuncSetAttribute(k_gemm, cudaFuncAttributeMaxDynamicSharedMemorySize,
                             GEMM_SMEM_BYTES);
    }

    // ---- fork ----
    cudaEventRecord(evFork, 0);
    cudaStreamWaitEvent(s2, evFork, 0);
    cudaStreamWaitEvent(s3, evFork, 0);

    // s2: node_feat zeroing + edge sort
    cudaMemsetAsync(node_feat, 0, (size_t)NN * ODIM * sizeof(float), s2);
    k_init<<<(EE + 255) / 256, 256, 0, s2>>>();
    k_hist<<<(PP + 255) / 256, 256, 0, s2>>>(edge_idx);
    k_scanA<<<SCAN_NB_E, SCAN_BLK, 0, s2>>>();
    k_scanB<<<1, 256, 0, s2>>>();
    k_scanC<<<(EE + 255) / 256, 256, 0, s2>>>();
    k_scatterE<<<(PP + 255) / 256, 256, 0, s2>>>(node_idx, edge_idx);
    cudaEventRecord(evE, s2);

    // s3: scores
    k_wctx<<<3, 256, 0, s3>>>(Wq, edge_ctx);
    k_score<<<(NN * 32 + 255) / 256, 256, 0, s3>>>(x);
    cudaEventRecord(evScore, s3);

    // main: dense pipeline
    k_pack<<<WROWS, 128>>>(Wv, fc1_w, type_query);
    k_gemm<<<(NN + GBM - 1) / GBM, 256, GEMM_SMEM_BYTES>>>(x);

    cudaStreamWaitEvent(0, evScore, 0);
    k_gate<<<(NN * 32 + 255) / 256, 256>>>(node_types, fc1_b, fc2_w, fc2_b);

    cudaStreamWaitEvent(0, evE, 0);
    k_passCD<<<(EE * 32 + 255) / 256, 256>>>(edge_type, edge_feat, node_feat);
}